// round 15
// baseline (speedup 1.0000x reference)
#include <cuda_runtime.h>
#include <cuda_bf16.h>
#include <math.h>

#define BSZ 2
#define SEQ 2048
#define DIM 1024
#define NH  16
#define HD  64
#define NTOK (BSZ*SEQ)            // 4096
#define NELEM ((size_t)NTOK*DIM)  // 4,194,304
#define WELEM ((size_t)DIM*DIM)   // 1,048,576

// Scratch (allocation-free rule: __device__ globals)
__device__ float g_M[NELEM];               // merged attention output [B,S,H*HD]
__device__ float g_Wt[4*WELEM];            // transposed+RNA-rounded weights [n][k]
__device__ __nv_bfloat16 g_Qh[NELEM], g_Ql[NELEM];
__device__ __nv_bfloat16 g_Kh[NELEM], g_Kl[NELEM];
__device__ __nv_bfloat16 g_Vh[NELEM], g_Vl[NELEM];

// ---------------------------------------------------------------------------
// small PTX helpers
// ---------------------------------------------------------------------------
__device__ __forceinline__ unsigned f2tf32(float f) {
    unsigned r;
    asm("cvt.rna.tf32.f32 %0, %1;" : "=r"(r) : "f"(f));
    return r;
}
__device__ __forceinline__ unsigned packbf2(float hi, float lo) {
    unsigned d;
    asm("cvt.rn.bf16x2.f32 %0, %1, %2;" : "=r"(d) : "f"(hi), "f"(lo));
    return d;
}
__device__ __forceinline__ void cp_async16(unsigned smem_addr, const void* gptr) {
    asm volatile("cp.async.cg.shared.global [%0], [%1], 16;\n"
                 :: "r"(smem_addr), "l"(gptr));
}
__device__ __forceinline__ void cp_commit() {
    asm volatile("cp.async.commit_group;\n");
}
template <int N>
__device__ __forceinline__ void cp_wait() {
    asm volatile("cp.async.wait_group %0;\n" :: "n"(N));
}
__device__ __forceinline__ void ldsm_x4(unsigned* r, unsigned addr) {
    asm volatile("ldmatrix.sync.aligned.m8n8.x4.shared.b16 {%0,%1,%2,%3}, [%4];"
                 : "=r"(r[0]), "=r"(r[1]), "=r"(r[2]), "=r"(r[3]) : "r"(addr));
}
__device__ __forceinline__ void ldsm_x4_t(unsigned* r, unsigned addr) {
    asm volatile("ldmatrix.sync.aligned.m8n8.x4.trans.shared.b16 {%0,%1,%2,%3}, [%4];"
                 : "=r"(r[0]), "=r"(r[1]), "=r"(r[2]), "=r"(r[3]) : "r"(addr));
}
__device__ __forceinline__ void mma_bf16(float* c, const unsigned* a,
                                         unsigned b0, unsigned b1) {
    asm volatile(
        "mma.sync.aligned.m16n8k16.row.col.f32.bf16.bf16.f32 "
        "{%0,%1,%2,%3},{%4,%5,%6,%7},{%8,%9},{%0,%1,%2,%3};"
        : "+f"(c[0]), "+f"(c[1]), "+f"(c[2]), "+f"(c[3])
        : "r"(a[0]), "r"(a[1]), "r"(a[2]), "r"(a[3]), "r"(b0), "r"(b1));
}
__device__ __forceinline__ void mma_tf32(float* c, const unsigned* a,
                                         unsigned b0, unsigned b1) {
    asm volatile(
        "mma.sync.aligned.m16n8k8.row.col.f32.tf32.tf32.f32 "
        "{%0,%1,%2,%3},{%4,%5,%6,%7},{%8,%9},{%0,%1,%2,%3};"
        : "+f"(c[0]), "+f"(c[1]), "+f"(c[2]), "+f"(c[3])
        : "r"(a[0]), "r"(a[1]), "r"(a[2]), "r"(a[3]), "r"(b0), "r"(b1));
}

// ---------------------------------------------------------------------------
// Pre-pass: W[k][n] -> Wt[n][k], RNA-rounded to the tf32 grid (fp32 storage).
// ---------------------------------------------------------------------------
__global__ void __launch_bounds__(1024)
wtrans(const float* __restrict__ Wq, const float* __restrict__ Wk,
       const float* __restrict__ Wv, const float* __restrict__ Wo,
       float* __restrict__ Wt)
{
    __shared__ float t[32][33];
    const int z = blockIdx.z;
    const float* W = (z == 0) ? Wq : (z == 1) ? Wk : (z == 2) ? Wv : Wo;
    const int n0 = blockIdx.x * 32, k0 = blockIdx.y * 32;
    const int tx = threadIdx.x, ty = threadIdx.y;

    t[ty][tx] = W[(size_t)(k0 + ty) * DIM + n0 + tx];
    __syncthreads();
    float val = t[tx][ty];   // = W[k0+tx][n0+ty] = Wt[n0+ty][k0+tx]
    Wt[(size_t)z * WELEM + (size_t)(n0 + ty) * DIM + k0 + tx] =
        __uint_as_float(f2tf32(val));
}

// ---------------------------------------------------------------------------
// TF32 GEMM core, ldmatrix operand path, 3-stage pipeline:
//   C[M,N] = A[M,K] @ B,  A row-major fp32 (raw; RNA cvt on fragments),
//   B given as Bt[n][k] fp32 (pre-rounded by wtrans).
// 64x128 CTA tile, 128 threads (4 warps, 32x64 warp tile), GBK=16,
// 3 stages, SINGLE barrier/iter, prefetch before compute, 4 CTAs/SM.
// Row stride 80B = 5 x 16B chunks -> LDSM bank groups 5r mod 8 bijective.
// ---------------------------------------------------------------------------
#define GBM 64
#define GBN 128
#define GBK 16
#define TRS 20                              // row stride in floats (80 B)
#define STAGE_FLOATS ((GBM + GBN) * TRS)    // 192*20 = 3840
#define NSTAGE 3
#define GEMM_SMEM (NSTAGE*STAGE_FLOATS*4)   // 46080 B

__device__ __forceinline__ void gemm_core(
    const float* __restrict__ A, const float* __restrict__ Bt,
    float* __restrict__ Cf,
    __nv_bfloat16* __restrict__ Ch, __nv_bfloat16* __restrict__ Cl,
    float scale, int M, int N, int K, float* sm)
{
    const int tid  = threadIdx.x;
    const int lane = tid & 31;
    const int warp = tid >> 5;           // 0..3
    const int wm   = warp >> 1;          // 0..1 (32 rows)
    const int wn   = warp & 1;           // 0..1 (64 cols)

    const int mBase = blockIdx.y * GBM;
    const int nBase = blockIdx.x * GBN;

    const float* Ab = A  + (size_t)mBase * K;
    const float* Bb = Bt + (size_t)nBase * K;

    unsigned smem_base;
    asm("{ .reg .u64 t; cvta.to.shared.u64 t, %1; cvt.u32.u64 %0, t; }"
        : "=r"(smem_base) : "l"(sm));

    float c[2][8][4];
    #pragma unroll
    for (int mt = 0; mt < 2; mt++)
        #pragma unroll
        for (int nt = 0; nt < 8; nt++)
            #pragma unroll
            for (int e = 0; e < 4; e++) c[mt][nt][e] = 0.0f;

    const int niter = K / GBK;           // 64

    // one k16 chunk: A 64 rows x 4 chunks = 256; B 128 rows x 4 chunks = 512
    auto load_stage = [&](int iter) {
        if (iter < niter) {
            const int k0 = iter * GBK;
            const int buf = iter % NSTAGE;
            unsigned aBase = smem_base + (unsigned)(buf * STAGE_FLOATS) * 4u;
            unsigned bBase = aBase + GBM * TRS * 4u;
            #pragma unroll
            for (int it = 0; it < 2; it++) {
                int idx = tid + 128 * it;    // 0..255
                int r = idx >> 2, ch = idx & 3;
                cp_async16(aBase + (unsigned)(r * 80 + ch * 16),
                           Ab + (size_t)r * K + k0 + ch * 4);
            }
            #pragma unroll
            for (int it = 0; it < 4; it++) {
                int idx = tid + 128 * it;    // 0..511
                int r = idx >> 2, ch = idx & 3;
                cp_async16(bBase + (unsigned)(r * 80 + ch * 16),
                           Bb + (size_t)r * K + k0 + ch * 4);
            }
        }
        cp_commit();   // exactly one group per call (possibly empty)
    };

    load_stage(0);
    load_stage(1);

    // Precompute per-lane ldmatrix offsets (relative to region bases)
    unsigned aOff[2], bOff[4];
    {
        int arow_l = (lane & 7) + ((lane >> 3) & 1) * 8;   // row within 16
        int achk   = ((lane >> 4) & 1) * 16;               // 0 or 16 B
        #pragma unroll
        for (int mt = 0; mt < 2; mt++) {
            int row = wm * 32 + mt * 16 + arow_l;
            aOff[mt] = (unsigned)(row * 80 + achk);
        }
        int brow_l = (lane & 7) + ((lane >> 4) & 1) * 8;
        int bchk   = ((lane >> 3) & 1) * 16;
        #pragma unroll
        for (int p = 0; p < 4; p++) {
            int row = wn * 64 + p * 16 + brow_l;
            bOff[p] = (unsigned)(row * 80 + bchk);
        }
    }

    for (int i = 0; i < niter; i++) {
        cp_wait<1>();          // stage i landed (stage i+1 may be in flight)
        __syncthreads();       // all warps finished reading stage i-1
        load_stage(i + 2);     // refill (i+2)%3 == (i-1)%3, BEFORE compute

        const int buf = i % NSTAGE;
        unsigned aBase = smem_base + (unsigned)(buf * STAGE_FLOATS) * 4u;
        unsigned bBase = aBase + GBM * TRS * 4u;

        #pragma unroll
        for (int kk = 0; kk < GBK / 8; kk++) {
            unsigned koff = (unsigned)(kk * 32);   // 8 tf32 = 32 B
            unsigned af[2][4], bf[4][4];
            #pragma unroll
            for (int mt = 0; mt < 2; mt++) {
                ldsm_x4(af[mt], aBase + aOff[mt] + koff);
                #pragma unroll
                for (int e = 0; e < 4; e++)
                    af[mt][e] = f2tf32(__uint_as_float(af[mt][e]));
            }
            #pragma unroll
            for (int p = 0; p < 4; p++)
                ldsm_x4(bf[p], bBase + bOff[p] + koff);

            #pragma unroll
            for (int mt = 0; mt < 2; mt++)
                #pragma unroll
                for (int nt = 0; nt < 8; nt++)
                    mma_tf32(c[mt][nt], af[mt],
                             bf[nt >> 1][2 * (nt & 1)],
                             bf[nt >> 1][2 * (nt & 1) + 1]);
        }
        // no trailing barrier: next iteration's barrier covers the hazard
        // (3 stages guarantee the refill target is not being read).
    }

    // Epilogue (same c-frag mapping as R8/R14)
    const int g  = lane >> 2;
    const int tg = lane & 3;
    if (Ch) {
        #pragma unroll
        for (int mt = 0; mt < 2; mt++) {
            int r0 = mBase + wm * 32 + mt * 16 + g;
            #pragma unroll
            for (int nt = 0; nt < 8; nt++) {
                int col = nBase + wn * 64 + nt * 8 + 2 * tg;
                #pragma unroll
                for (int half = 0; half < 2; half++) {
                    size_t off = (size_t)(r0 + 8 * half) * N + col;
                    float y0 = c[mt][nt][2 * half + 0] * scale;
                    float y1 = c[mt][nt][2 * half + 1] * scale;
                    unsigned hi = packbf2(y1, y0);
                    float h0 = __uint_as_float(hi << 16);
                    float h1 = __uint_as_float(hi & 0xffff0000u);
                    unsigned lo = packbf2(y1 - h1, y0 - h0);
                    *(unsigned*)(Ch + off) = hi;
                    *(unsigned*)(Cl + off) = lo;
                }
            }
        }
    } else {
        #pragma unroll
        for (int mt = 0; mt < 2; mt++) {
            int r0 = mBase + wm * 32 + mt * 16 + g;
            #pragma unroll
            for (int nt = 0; nt < 8; nt++) {
                int col = nBase + wn * 64 + nt * 8 + 2 * tg;
                *(float2*)(Cf + (size_t)r0 * N + col) =
                    make_float2(c[mt][nt][0], c[mt][nt][1]);
                *(float2*)(Cf + (size_t)(r0 + 8) * N + col) =
                    make_float2(c[mt][nt][2], c[mt][nt][3]);
            }
        }
    }
}

// Fused Q/K/V projections: grid.z selects the GEMM.
__global__ void __launch_bounds__(128, 4)
qkv_gemm(const float* __restrict__ q, const float* __restrict__ k,
         const float* __restrict__ v, const float* __restrict__ Wt,
         __nv_bfloat16* Qh, __nv_bfloat16* Ql,
         __nv_bfloat16* Kh, __nv_bfloat16* Kl,
         __nv_bfloat16* Vh, __nv_bfloat16* Vl)
{
    extern __shared__ float sm[];
    const int z = blockIdx.z;
    const float* A = (z == 0) ? q  : (z == 1) ? k  : v;
    __nv_bfloat16* Ch = (z == 0) ? Qh : (z == 1) ? Kh : Vh;
    __nv_bfloat16* Cl = (z == 0) ? Ql : (z == 1) ? Kl : Vl;
    float scale = (z == 0) ? 0.125f : 1.0f;
    gemm_core(A, Wt + (size_t)z * WELEM, nullptr, Ch, Cl, scale,
              NTOK, DIM, DIM, sm);
}

__global__ void __launch_bounds__(128, 4)
wo_gemm(const float* __restrict__ A, const float* __restrict__ Wt,
        float* __restrict__ C)
{
    extern __shared__ float sm[];
    gemm_core(A, Wt + 3 * WELEM, C, nullptr, nullptr, 1.0f,
              NTOK, DIM, DIM, sm);
}

// ---------------------------------------------------------------------------
// Flash attention (exact R8 config — best measured): bf16 tensor cores,
// 3-term hi/lo split, 128-thread CTAs over 64 q-rows, 2 CTAs/SM,
// gmem-direct Q frags, 2-stage cp.async KV double-buffer, padded smem.
// ---------------------------------------------------------------------------
#define RS 72
#define KVSTAGE (4*64*RS)              // 18432 bf16 per stage
#define SB_TOTAL (2*KVSTAGE)           // 73728 B
#define OKH 0
#define OKL (64*RS)
#define OVH (128*RS)
#define OVL (192*RS)

__global__ void __launch_bounds__(128, 2)
flash_bf16(const __nv_bfloat16* __restrict__ Qh, const __nv_bfloat16* __restrict__ Ql,
           const __nv_bfloat16* __restrict__ Kh, const __nv_bfloat16* __restrict__ Kl,
           const __nv_bfloat16* __restrict__ Vh, const __nv_bfloat16* __restrict__ Vl,
           float* __restrict__ merged, float* __restrict__ attn_out,
           int write_attn, const int* __restrict__ maskedp)
{
    extern __shared__ __nv_bfloat16 sb[];
    const int qt  = gridDim.x - 1 - blockIdx.x;   // heavy blocks first
    const int h   = blockIdx.y;
    const int b   = blockIdx.z;
    const int tid = threadIdx.x;
    const int lane = tid & 31;
    const int w   = tid >> 5;                     // 0..3
    const int q0  = qt * 64;
    const int masked = maskedp[0];

    unsigned sbase;
    asm("{ .reg .u64 t; cvta.to.shared.u64 t, %1; cvt.u32.u64 %0, t; }"
        : "=r"(sbase) : "l"(sb));

    const int ktmax = masked ? qt : (SEQ / 64 - 1);

    auto stage_off = [](int kt) -> unsigned { return (kt & 1) ? (unsigned)KVSTAGE : 0u; };

    auto prefetch = [&](int t) {
        if (t <= ktmax) {
            unsigned so = stage_off(t);
            int r  = tid >> 3;
            int c8 = (tid & 7) << 3;
            #pragma unroll
            for (int quarter = 0; quarter < 4; quarter++) {
                int rr = r + 16 * quarter;
                size_t gidx = ((size_t)(b * SEQ + t * 64 + rr) * DIM) + h * HD + c8;
                unsigned sa = sbase + (so + rr * RS + c8) * 2;
                cp_async16(sa + OKH * 2, Kh + gidx);
                cp_async16(sa + OKL * 2, Kl + gidx);
                cp_async16(sa + OVH * 2, Vh + gidx);
                cp_async16(sa + OVL * 2, Vl + gidx);
            }
        }
        cp_commit();
    };

    prefetch(0);
    prefetch(1);

    unsigned qf[2][4][4];
    {
        const int g  = lane >> 2;
        const int tg = lane & 3;
        const int row0 = q0 + 16 * w + g;
        size_t base0 = ((size_t)(b * SEQ + row0)     * DIM) + h * HD;
        size_t base1 = ((size_t)(b * SEQ + row0 + 8) * DIM) + h * HD;
        #pragma unroll
        for (int d = 0; d < 4; d++) {
            int c0 = 16 * d + 2 * tg;
            qf[0][d][0] = *(const unsigned*)(Qh + base0 + c0);
            qf[0][d][1] = *(const unsigned*)(Qh + base1 + c0);
            qf[0][d][2] = *(const unsigned*)(Qh + base0 + c0 + 8);
            qf[0][d][3] = *(const unsigned*)(Qh + base1 + c0 + 8);
            qf[1][d][0] = *(const unsigned*)(Ql + base0 + c0);
            qf[1][d][1] = *(const unsigned*)(Ql + base1 + c0);
            qf[1][d][2] = *(const unsigned*)(Ql + base0 + c0 + 8);
            qf[1][d][3] = *(const unsigned*)(Ql + base1 + c0 + 8);
        }
    }

    float o[8][4];
    #pragma unroll
    for (int j = 0; j < 8; j++)
        #pragma unroll
        for (int e = 0; e < 4; e++) o[j][e] = 0.0f;
    float m0 = -1e30f, m1 = -1e30f, l0 = 0.0f, l1 = 0.0f;

    const int r_lo = q0 + 16 * w + (lane >> 2);
    const int r_hi = r_lo + 8;

    for (int kt = 0; kt <= ktmax; kt++) {
        cp_wait<1>();
        __syncthreads();

        const unsigned so = stage_off(kt);
        const int k0 = kt * 64;

        float s[8][4];
        #pragma unroll
        for (int j = 0; j < 8; j++)
            #pragma unroll
            for (int e = 0; e < 4; e++) s[j][e] = 0.0f;

        #pragma unroll
        for (int j = 0; j < 8; j++) {
            unsigned kbh[8], kbl[8];
            int krow = 8 * j + (lane & 7);
            int dct  = (lane >> 3) << 3;
            ldsm_x4(&kbh[0], sbase + (so + OKH + krow * RS + dct) * 2);
            ldsm_x4(&kbh[4], sbase + (so + OKH + krow * RS + 32 + dct) * 2);
            ldsm_x4(&kbl[0], sbase + (so + OKL + krow * RS + dct) * 2);
            ldsm_x4(&kbl[4], sbase + (so + OKL + krow * RS + 32 + dct) * 2);
            #pragma unroll
            for (int d = 0; d < 4; d++) {
                mma_bf16(s[j], qf[0][d], kbh[2*d], kbh[2*d+1]);
                mma_bf16(s[j], qf[0][d], kbl[2*d], kbl[2*d+1]);
                mma_bf16(s[j], qf[1][d], kbh[2*d], kbh[2*d+1]);
            }
        }

        if (masked && kt == qt) {
            #pragma unroll
            for (int j = 0; j < 8; j++) {
                int cc = k0 + 8 * j + 2 * (lane & 3);
                if (cc     > r_lo) s[j][0] = -1e30f;
                if (cc + 1 > r_lo) s[j][1] = -1e30f;
                if (cc     > r_hi) s[j][2] = -1e30f;
                if (cc + 1 > r_hi) s[j][3] = -1e30f;
            }
        }

        float mt0 = -1e30f, mt1 = -1e30f;
        #pragma unroll
        for (int j = 0; j < 8; j++) {
            mt0 = fmaxf(mt0, fmaxf(s[j][0], s[j][1]));
            mt1 = fmaxf(mt1, fmaxf(s[j][2], s[j][3]));
        }
        mt0 = fmaxf(mt0, __shfl_xor_sync(0xffffffffu, mt0, 1));
        mt0 = fmaxf(mt0, __shfl_xor_sync(0xffffffffu, mt0, 2));
        mt1 = fmaxf(mt1, __shfl_xor_sync(0xffffffffu, mt1, 1));
        mt1 = fmaxf(mt1, __shfl_xor_sync(0xffffffffu, mt1, 2));
        float mn0 = fmaxf(m0, mt0), mn1 = fmaxf(m1, mt1);
        float a0 = __expf(m0 - mn0), a1 = __expf(m1 - mn1);
        m0 = mn0; m1 = mn1;

        float rs0 = 0.0f, rs1 = 0.0f;
        unsigned pah[4][4], pal[4][4];
        #pragma unroll
        for (int j = 0; j < 8; j++) {
            float p0 = __expf(s[j][0] - mn0);
            float p1 = __expf(s[j][1] - mn0);
            float p2 = __expf(s[j][2] - mn1);
            float p3 = __expf(s[j][3] - mn1);
            rs0 += p0 + p1; rs1 += p2 + p3;
            unsigned h01 = packbf2(p1, p0);
            unsigned h23 = packbf2(p3, p2);
            float q0f = __uint_as_float(h01 << 16);
            float q1f = __uint_as_float(h01 & 0xffff0000u);
            float q2f = __uint_as_float(h23 << 16);
            float q3f = __uint_as_float(h23 & 0xffff0000u);
            unsigned lo01 = packbf2(p1 - q1f, p0 - q0f);
            unsigned lo23 = packbf2(p3 - q3f, p2 - q2f);
            int t = j >> 1, half = j & 1;
            pah[t][2 * half + 0] = h01;
            pah[t][2 * half + 1] = h23;
            pal[t][2 * half + 0] = lo01;
            pal[t][2 * half + 1] = lo23;
        }
        rs0 += __shfl_xor_sync(0xffffffffu, rs0, 1);
        rs0 += __shfl_xor_sync(0xffffffffu, rs0, 2);
        rs1 += __shfl_xor_sync(0xffffffffu, rs1, 1);
        rs1 += __shfl_xor_sync(0xffffffffu, rs1, 2);
        l0 = l0 * a0 + rs0;
        l1 = l1 * a1 + rs1;
        #pragma unroll
        for (int j = 0; j < 8; j++) {
            o[j][0] *= a0; o[j][1] *= a0;
            o[j][2] *= a1; o[j][3] *= a1;
        }

        #pragma unroll
        for (int jn = 0; jn < 8; jn++) {
            unsigned vbh[8], vbl[8];
            ldsm_x4_t(&vbh[0], sbase + (so + OVH + lane * RS + 8 * jn) * 2);
            ldsm_x4_t(&vbh[4], sbase + (so + OVH + (32 + lane) * RS + 8 * jn) * 2);
            ldsm_x4_t(&vbl[0], sbase + (so + OVL + lane * RS + 8 * jn) * 2);
            ldsm_x4_t(&vbl[4], sbase + (so + OVL + (32 + lane) * RS + 8 * jn) * 2);
            #pragma unroll
            for (int t = 0; t < 4; t++) {
                mma_bf16(o[jn], pah[t], vbh[2*t], vbh[2*t+1]);
                mma_bf16(o[jn], pah[t], vbl[2*t], vbl[2*t+1]);
                mma_bf16(o[jn], pal[t], vbh[2*t], vbh[2*t+1]);
            }
        }

        __syncthreads();
        prefetch(kt + 2);
    }

    float il0 = 1.0f / l0, il1 = 1.0f / l1;
    #pragma unroll
    for (int jn = 0; jn < 8; jn++) {
        int col = 8 * jn + 2 * (lane & 3);
        float f00 = o[jn][0] * il0, f01 = o[jn][1] * il0;
        float f10 = o[jn][2] * il1, f11 = o[jn][3] * il1;
        *(float2*)(merged + ((size_t)(b * SEQ + r_lo) * DIM) + h * HD + col) =
            make_float2(f00, f01);
        *(float2*)(merged + ((size_t)(b * SEQ + r_hi) * DIM) + h * HD + col) =
            make_float2(f10, f11);
        if (write_attn) {
            *(float2*)(attn_out + (((size_t)(b * NH + h) * SEQ + r_lo) * HD) + col) =
                make_float2(f00, f01);
            *(float2*)(attn_out + (((size_t)(b * NH + h) * SEQ + r_hi) * HD) + col) =
                make_float2(f10, f11);
        }
    }
}

// ---------------------------------------------------------------------------
extern "C" void kernel_launch(void* const* d_in, const int* in_sizes, int n_in,
                              void* d_out, int out_size)
{
    const float* q  = (const float*)d_in[0];
    const float* k  = (const float*)d_in[1];
    const float* v  = (const float*)d_in[2];
    const float* Wq = (const float*)d_in[3];
    const float* Wk = (const float*)d_in[4];
    const float* Wv = (const float*)d_in[5];
    const float* Wo = (const float*)d_in[6];
    const int* masked = (const int*)d_in[7];
    float* out = (float*)d_out;

    float *pM, *pWt;
    __nv_bfloat16 *pQh, *pQl, *pKh, *pKl, *pVh, *pVl;
    cudaGetSymbolAddress((void**)&pM,  g_M);
    cudaGetSymbolAddress((void**)&pWt, g_Wt);
    cudaGetSymbolAddress((void**)&pQh, g_Qh);
    cudaGetSymbolAddress((void**)&pQl, g_Ql);
    cudaGetSymbolAddress((void**)&pKh, g_Kh);
    cudaGetSymbolAddress((void**)&pKl, g_Kl);
    cudaGetSymbolAddress((void**)&pVh, g_Vh);
    cudaGetSymbolAddress((void**)&pVl, g_Vl);

    cudaFuncSetAttribute(qkv_gemm, cudaFuncAttributeMaxDynamicSharedMemorySize,
                         GEMM_SMEM);
    cudaFuncSetAttribute(wo_gemm, cudaFuncAttributeMaxDynamicSharedMemorySize,
                         GEMM_SMEM);

    // Pre-pass: transpose + RNA-round all 4 weight matrices
    dim3 gTr(DIM / 32, DIM / 32, 4);
    wtrans<<<gTr, dim3(32, 32)>>>(Wq, Wk, Wv, Wo, pWt);

    // Fused Q/K/V projections (ldmatrix tf32 core, 3-stage pipeline)
    dim3 gQKV(DIM / GBN, NTOK / GBM, 3);   // (8, 64, 3)
    qkv_gemm<<<gQKV, 128, GEMM_SMEM>>>(q, k, v, pWt,
                                       pQh, pQl, pKh, pKl, pVh, pVl);

    // Attention (exact R8 config)
    int write_attn = (out_size >= (int)(2 * NELEM)) ? 1 : 0;
    float* attn_ptr = out + NELEM;
    size_t fl_smem = (size_t)SB_TOTAL * sizeof(__nv_bfloat16);
    cudaFuncSetAttribute(flash_bf16, cudaFuncAttributeMaxDynamicSharedMemorySize,
                         (int)fl_smem);
    dim3 gAttn(SEQ / 64, NH, BSZ);         // (32, 16, 2)
    flash_bf16<<<gAttn, 128, fl_smem>>>(pQh, pQl, pKh, pKl, pVh, pVl,
                                        pM, attn_ptr, write_attn, masked);

    // Output projection (ldmatrix tf32 core, 3-stage pipeline)
    dim3 gWo(DIM / GBN, NTOK / GBM);       // (8, 64)
    wo_gemm<<<gWo, 128, GEMM_SMEM>>>(pM, pWt, out);
}

// round 16
// speedup vs baseline: 1.0264x; 1.0264x over previous
#include <cuda_runtime.h>
#include <cuda_bf16.h>
#include <math.h>

#define BSZ 2
#define SEQ 2048
#define DIM 1024
#define NH  16
#define HD  64
#define NTOK (BSZ*SEQ)            // 4096
#define NELEM ((size_t)NTOK*DIM)  // 4,194,304
#define WELEM ((size_t)DIM*DIM)   // 1,048,576

// Scratch (allocation-free rule: __device__ globals)
__device__ float g_M[NELEM];               // merged attention output [B,S,H*HD]
__device__ float g_Wt[4*WELEM];            // transposed+RNA-rounded weights [n][k]
__device__ __nv_bfloat16 g_Qh[NELEM], g_Ql[NELEM];
__device__ __nv_bfloat16 g_Kh[NELEM], g_Kl[NELEM];
__device__ __nv_bfloat16 g_Vh[NELEM], g_Vl[NELEM];

// ---------------------------------------------------------------------------
// small PTX helpers
// ---------------------------------------------------------------------------
__device__ __forceinline__ unsigned f2tf32(float f) {
    unsigned r;
    asm("cvt.rna.tf32.f32 %0, %1;" : "=r"(r) : "f"(f));
    return r;
}
__device__ __forceinline__ unsigned packbf2(float hi, float lo) {
    unsigned d;
    asm("cvt.rn.bf16x2.f32 %0, %1, %2;" : "=r"(d) : "f"(hi), "f"(lo));
    return d;
}
__device__ __forceinline__ void cp_async16(unsigned smem_addr, const void* gptr) {
    asm volatile("cp.async.cg.shared.global [%0], [%1], 16;\n"
                 :: "r"(smem_addr), "l"(gptr));
}
__device__ __forceinline__ void cp_commit() {
    asm volatile("cp.async.commit_group;\n");
}
template <int N>
__device__ __forceinline__ void cp_wait() {
    asm volatile("cp.async.wait_group %0;\n" :: "n"(N));
}
__device__ __forceinline__ void ldsm_x4(unsigned* r, unsigned addr) {
    asm volatile("ldmatrix.sync.aligned.m8n8.x4.shared.b16 {%0,%1,%2,%3}, [%4];"
                 : "=r"(r[0]), "=r"(r[1]), "=r"(r[2]), "=r"(r[3]) : "r"(addr));
}
__device__ __forceinline__ void ldsm_x4_t(unsigned* r, unsigned addr) {
    asm volatile("ldmatrix.sync.aligned.m8n8.x4.trans.shared.b16 {%0,%1,%2,%3}, [%4];"
                 : "=r"(r[0]), "=r"(r[1]), "=r"(r[2]), "=r"(r[3]) : "r"(addr));
}
__device__ __forceinline__ void mma_bf16(float* c, const unsigned* a,
                                         unsigned b0, unsigned b1) {
    asm volatile(
        "mma.sync.aligned.m16n8k16.row.col.f32.bf16.bf16.f32 "
        "{%0,%1,%2,%3},{%4,%5,%6,%7},{%8,%9},{%0,%1,%2,%3};"
        : "+f"(c[0]), "+f"(c[1]), "+f"(c[2]), "+f"(c[3])
        : "r"(a[0]), "r"(a[1]), "r"(a[2]), "r"(a[3]), "r"(b0), "r"(b1));
}
__device__ __forceinline__ void mma_tf32(float* c, const unsigned* a,
                                         unsigned b0, unsigned b1) {
    asm volatile(
        "mma.sync.aligned.m16n8k8.row.col.f32.tf32.tf32.f32 "
        "{%0,%1,%2,%3},{%4,%5,%6,%7},{%8,%9},{%0,%1,%2,%3};"
        : "+f"(c[0]), "+f"(c[1]), "+f"(c[2]), "+f"(c[3])
        : "r"(a[0]), "r"(a[1]), "r"(a[2]), "r"(a[3]), "r"(b0), "r"(b1));
}

// ---------------------------------------------------------------------------
// Pre-pass: W[k][n] -> Wt[n][k], RNA-rounded to the tf32 grid (fp32 storage).
// ---------------------------------------------------------------------------
__global__ void __launch_bounds__(1024)
wtrans(const float* __restrict__ Wq, const float* __restrict__ Wk,
       const float* __restrict__ Wv, const float* __restrict__ Wo,
       float* __restrict__ Wt)
{
    __shared__ float t[32][33];
    const int z = blockIdx.z;
    const float* W = (z == 0) ? Wq : (z == 1) ? Wk : (z == 2) ? Wv : Wo;
    const int n0 = blockIdx.x * 32, k0 = blockIdx.y * 32;
    const int tx = threadIdx.x, ty = threadIdx.y;

    t[ty][tx] = W[(size_t)(k0 + ty) * DIM + n0 + tx];
    __syncthreads();
    float val = t[tx][ty];
    Wt[(size_t)z * WELEM + (size_t)(n0 + ty) * DIM + k0 + tx] =
        __uint_as_float(f2tf32(val));
}

// ---------------------------------------------------------------------------
// TF32 GEMM core, ldmatrix operand path, GBK=32, 3-stage single-barrier
// pipeline with prefetch-before-compute. 128x128 CTA tile, 256 threads
// (8 warps, 32x64 warp tile — identical per-warp stream to R14), 2 CTAs/SM.
// Row stride 144B = 9 x 16B chunks -> LDSM conflict-free.
// ---------------------------------------------------------------------------
#define GBM 128
#define GBN 128
#define GBK 32
#define TRS 36                              // row stride in floats (144 B)
#define STAGE_FLOATS ((GBM + GBN) * TRS)    // 256*36 = 9216
#define NSTAGE 3
#define GEMM_SMEM (NSTAGE*STAGE_FLOATS*4)   // 110592 B

__device__ __forceinline__ void gemm_core(
    const float* __restrict__ A, const float* __restrict__ Bt,
    float* __restrict__ Cf,
    __nv_bfloat16* __restrict__ Ch, __nv_bfloat16* __restrict__ Cl,
    float scale, int M, int N, int K, float* sm)
{
    const int tid  = threadIdx.x;
    const int lane = tid & 31;
    const int warp = tid >> 5;           // 0..7
    const int wm   = warp >> 1;          // 0..3 (32 rows each)
    const int wn   = warp & 1;           // 0..1 (64 cols each)

    const int mBase = blockIdx.y * GBM;
    const int nBase = blockIdx.x * GBN;

    const float* Ab = A  + (size_t)mBase * K;
    const float* Bb = Bt + (size_t)nBase * K;

    unsigned smem_base;
    asm("{ .reg .u64 t; cvta.to.shared.u64 t, %1; cvt.u32.u64 %0, t; }"
        : "=r"(smem_base) : "l"(sm));

    float c[2][8][4];
    #pragma unroll
    for (int mt = 0; mt < 2; mt++)
        #pragma unroll
        for (int nt = 0; nt < 8; nt++)
            #pragma unroll
            for (int e = 0; e < 4; e++) c[mt][nt][e] = 0.0f;

    const int niter = K / GBK;           // 32

    // one k32 chunk: A 128 rows x 8 chunks = 1024; B 128 rows x 8 = 1024
    auto load_stage = [&](int iter) {
        const int k0 = iter * GBK;
        const int buf = iter % NSTAGE;
        unsigned aBase = smem_base + (unsigned)(buf * STAGE_FLOATS) * 4u;
        unsigned bBase = aBase + GBM * TRS * 4u;
        #pragma unroll
        for (int it = 0; it < 4; it++) {
            int idx = tid + 256 * it;    // 0..1023
            int r = idx >> 3, ch = idx & 7;
            cp_async16(aBase + (unsigned)(r * 144 + ch * 16),
                       Ab + (size_t)r * K + k0 + ch * 4);
        }
        #pragma unroll
        for (int it = 0; it < 4; it++) {
            int idx = tid + 256 * it;
            int r = idx >> 3, ch = idx & 7;
            cp_async16(bBase + (unsigned)(r * 144 + ch * 16),
                       Bb + (size_t)r * K + k0 + ch * 4);
        }
    };

    load_stage(0); cp_commit();
    load_stage(1); cp_commit();

    // Precompute per-lane ldmatrix offsets (relative to region bases)
    unsigned aOff[2], bOff[4];
    {
        int arow_l = (lane & 7) + ((lane >> 3) & 1) * 8;
        int achk   = ((lane >> 4) & 1) * 16;
        #pragma unroll
        for (int mt = 0; mt < 2; mt++) {
            int row = wm * 32 + mt * 16 + arow_l;
            aOff[mt] = (unsigned)(row * 144 + achk);
        }
        int brow_l = (lane & 7) + ((lane >> 4) & 1) * 8;
        int bchk   = ((lane >> 3) & 1) * 16;
        #pragma unroll
        for (int p = 0; p < 4; p++) {
            int row = wn * 64 + p * 16 + brow_l;
            bOff[p] = (unsigned)(row * 144 + bchk);
        }
    }

    for (int i = 0; i < niter; i++) {
        cp_wait<1>();          // stage i landed (stage i+1 may be in flight)
        __syncthreads();       // all warps finished compute of iter i-1
        if (i + 2 < niter) load_stage(i + 2);   // into (i+2)%3 == (i-1)%3
        cp_commit();           // exactly one group per iteration

        const int buf = i % NSTAGE;
        unsigned aBase = smem_base + (unsigned)(buf * STAGE_FLOATS) * 4u;
        unsigned bBase = aBase + GBM * TRS * 4u;

        #pragma unroll
        for (int kk = 0; kk < GBK / 8; kk++) {
            unsigned koff = (unsigned)(kk * 32);   // 8 tf32 = 32 B
            unsigned af[2][4], bf[4][4];
            #pragma unroll
            for (int mt = 0; mt < 2; mt++) {
                ldsm_x4(af[mt], aBase + aOff[mt] + koff);
                #pragma unroll
                for (int e = 0; e < 4; e++)
                    af[mt][e] = f2tf32(__uint_as_float(af[mt][e]));
            }
            #pragma unroll
            for (int p = 0; p < 4; p++)
                ldsm_x4(bf[p], bBase + bOff[p] + koff);

            #pragma unroll
            for (int mt = 0; mt < 2; mt++)
                #pragma unroll
                for (int nt = 0; nt < 8; nt++)
                    mma_tf32(c[mt][nt], af[mt],
                             bf[nt >> 1][2 * (nt & 1)],
                             bf[nt >> 1][2 * (nt & 1) + 1]);
        }
        // no trailing barrier: next iteration's barrier covers the hazard
        // (3 stages guarantee the refill target is not being read).
    }

    // Epilogue
    const int g  = lane >> 2;
    const int tg = lane & 3;
    if (Ch) {
        #pragma unroll
        for (int mt = 0; mt < 2; mt++) {
            int r0 = mBase + wm * 32 + mt * 16 + g;
            #pragma unroll
            for (int nt = 0; nt < 8; nt++) {
                int col = nBase + wn * 64 + nt * 8 + 2 * tg;
                #pragma unroll
                for (int half = 0; half < 2; half++) {
                    size_t off = (size_t)(r0 + 8 * half) * N + col;
                    float y0 = c[mt][nt][2 * half + 0] * scale;
                    float y1 = c[mt][nt][2 * half + 1] * scale;
                    unsigned hi = packbf2(y1, y0);
                    float h0 = __uint_as_float(hi << 16);
                    float h1 = __uint_as_float(hi & 0xffff0000u);
                    unsigned lo = packbf2(y1 - h1, y0 - h0);
                    *(unsigned*)(Ch + off) = hi;
                    *(unsigned*)(Cl + off) = lo;
                }
            }
        }
    } else {
        #pragma unroll
        for (int mt = 0; mt < 2; mt++) {
            int r0 = mBase + wm * 32 + mt * 16 + g;
            #pragma unroll
            for (int nt = 0; nt < 8; nt++) {
                int col = nBase + wn * 64 + nt * 8 + 2 * tg;
                *(float2*)(Cf + (size_t)r0 * N + col) =
                    make_float2(c[mt][nt][0], c[mt][nt][1]);
                *(float2*)(Cf + (size_t)(r0 + 8) * N + col) =
                    make_float2(c[mt][nt][2], c[mt][nt][3]);
            }
        }
    }
}

// Fused Q/K/V projections: grid.z selects the GEMM.
__global__ void __launch_bounds__(256, 2)
qkv_gemm(const float* __restrict__ q, const float* __restrict__ k,
         const float* __restrict__ v, const float* __restrict__ Wt,
         __nv_bfloat16* Qh, __nv_bfloat16* Ql,
         __nv_bfloat16* Kh, __nv_bfloat16* Kl,
         __nv_bfloat16* Vh, __nv_bfloat16* Vl)
{
    extern __shared__ float sm[];
    const int z = blockIdx.z;
    const float* A = (z == 0) ? q  : (z == 1) ? k  : v;
    __nv_bfloat16* Ch = (z == 0) ? Qh : (z == 1) ? Kh : Vh;
    __nv_bfloat16* Cl = (z == 0) ? Ql : (z == 1) ? Kl : Vl;
    float scale = (z == 0) ? 0.125f : 1.0f;
    gemm_core(A, Wt + (size_t)z * WELEM, nullptr, Ch, Cl, scale,
              NTOK, DIM, DIM, sm);
}

__global__ void __launch_bounds__(256, 2)
wo_gemm(const float* __restrict__ A, const float* __restrict__ Wt,
        float* __restrict__ C)
{
    extern __shared__ float sm[];
    gemm_core(A, Wt + 3 * WELEM, C, nullptr, nullptr, 1.0f,
              NTOK, DIM, DIM, sm);
}

// ---------------------------------------------------------------------------
// Flash attention (exact R8 config — best measured): bf16 tensor cores,
// 3-term hi/lo split, 128-thread CTAs over 64 q-rows, 2 CTAs/SM,
// gmem-direct Q frags, 2-stage cp.async KV double-buffer, padded smem.
// ---------------------------------------------------------------------------
#define RS 72
#define KVSTAGE (4*64*RS)              // 18432 bf16 per stage
#define SB_TOTAL (2*KVSTAGE)           // 73728 B
#define OKH 0
#define OKL (64*RS)
#define OVH (128*RS)
#define OVL (192*RS)

__global__ void __launch_bounds__(128, 2)
flash_bf16(const __nv_bfloat16* __restrict__ Qh, const __nv_bfloat16* __restrict__ Ql,
           const __nv_bfloat16* __restrict__ Kh, const __nv_bfloat16* __restrict__ Kl,
           const __nv_bfloat16* __restrict__ Vh, const __nv_bfloat16* __restrict__ Vl,
           float* __restrict__ merged, float* __restrict__ attn_out,
           int write_attn, const int* __restrict__ maskedp)
{
    extern __shared__ __nv_bfloat16 sb[];
    const int qt  = gridDim.x - 1 - blockIdx.x;   // heavy blocks first
    const int h   = blockIdx.y;
    const int b   = blockIdx.z;
    const int tid = threadIdx.x;
    const int lane = tid & 31;
    const int w   = tid >> 5;                     // 0..3
    const int q0  = qt * 64;
    const int masked = maskedp[0];

    unsigned sbase;
    asm("{ .reg .u64 t; cvta.to.shared.u64 t, %1; cvt.u32.u64 %0, t; }"
        : "=r"(sbase) : "l"(sb));

    const int ktmax = masked ? qt : (SEQ / 64 - 1);

    auto stage_off = [](int kt) -> unsigned { return (kt & 1) ? (unsigned)KVSTAGE : 0u; };

    auto prefetch = [&](int t) {
        if (t <= ktmax) {
            unsigned so = stage_off(t);
            int r  = tid >> 3;
            int c8 = (tid & 7) << 3;
            #pragma unroll
            for (int quarter = 0; quarter < 4; quarter++) {
                int rr = r + 16 * quarter;
                size_t gidx = ((size_t)(b * SEQ + t * 64 + rr) * DIM) + h * HD + c8;
                unsigned sa = sbase + (so + rr * RS + c8) * 2;
                cp_async16(sa + OKH * 2, Kh + gidx);
                cp_async16(sa + OKL * 2, Kl + gidx);
                cp_async16(sa + OVH * 2, Vh + gidx);
                cp_async16(sa + OVL * 2, Vl + gidx);
            }
        }
        cp_commit();
    };

    prefetch(0);
    prefetch(1);

    unsigned qf[2][4][4];
    {
        const int g  = lane >> 2;
        const int tg = lane & 3;
        const int row0 = q0 + 16 * w + g;
        size_t base0 = ((size_t)(b * SEQ + row0)     * DIM) + h * HD;
        size_t base1 = ((size_t)(b * SEQ + row0 + 8) * DIM) + h * HD;
        #pragma unroll
        for (int d = 0; d < 4; d++) {
            int c0 = 16 * d + 2 * tg;
            qf[0][d][0] = *(const unsigned*)(Qh + base0 + c0);
            qf[0][d][1] = *(const unsigned*)(Qh + base1 + c0);
            qf[0][d][2] = *(const unsigned*)(Qh + base0 + c0 + 8);
            qf[0][d][3] = *(const unsigned*)(Qh + base1 + c0 + 8);
            qf[1][d][0] = *(const unsigned*)(Ql + base0 + c0);
            qf[1][d][1] = *(const unsigned*)(Ql + base1 + c0);
            qf[1][d][2] = *(const unsigned*)(Ql + base0 + c0 + 8);
            qf[1][d][3] = *(const unsigned*)(Ql + base1 + c0 + 8);
        }
    }

    float o[8][4];
    #pragma unroll
    for (int j = 0; j < 8; j++)
        #pragma unroll
        for (int e = 0; e < 4; e++) o[j][e] = 0.0f;
    float m0 = -1e30f, m1 = -1e30f, l0 = 0.0f, l1 = 0.0f;

    const int r_lo = q0 + 16 * w + (lane >> 2);
    const int r_hi = r_lo + 8;

    for (int kt = 0; kt <= ktmax; kt++) {
        cp_wait<1>();
        __syncthreads();

        const unsigned so = stage_off(kt);
        const int k0 = kt * 64;

        float s[8][4];
        #pragma unroll
        for (int j = 0; j < 8; j++)
            #pragma unroll
            for (int e = 0; e < 4; e++) s[j][e] = 0.0f;

        #pragma unroll
        for (int j = 0; j < 8; j++) {
            unsigned kbh[8], kbl[8];
            int krow = 8 * j + (lane & 7);
            int dct  = (lane >> 3) << 3;
            ldsm_x4(&kbh[0], sbase + (so + OKH + krow * RS + dct) * 2);
            ldsm_x4(&kbh[4], sbase + (so + OKH + krow * RS + 32 + dct) * 2);
            ldsm_x4(&kbl[0], sbase + (so + OKL + krow * RS + dct) * 2);
            ldsm_x4(&kbl[4], sbase + (so + OKL + krow * RS + 32 + dct) * 2);
            #pragma unroll
            for (int d = 0; d < 4; d++) {
                mma_bf16(s[j], qf[0][d], kbh[2*d], kbh[2*d+1]);
                mma_bf16(s[j], qf[0][d], kbl[2*d], kbl[2*d+1]);
                mma_bf16(s[j], qf[1][d], kbh[2*d], kbh[2*d+1]);
            }
        }

        if (masked && kt == qt) {
            #pragma unroll
            for (int j = 0; j < 8; j++) {
                int cc = k0 + 8 * j + 2 * (lane & 3);
                if (cc     > r_lo) s[j][0] = -1e30f;
                if (cc + 1 > r_lo) s[j][1] = -1e30f;
                if (cc     > r_hi) s[j][2] = -1e30f;
                if (cc + 1 > r_hi) s[j][3] = -1e30f;
            }
        }

        float mt0 = -1e30f, mt1 = -1e30f;
        #pragma unroll
        for (int j = 0; j < 8; j++) {
            mt0 = fmaxf(mt0, fmaxf(s[j][0], s[j][1]));
            mt1 = fmaxf(mt1, fmaxf(s[j][2], s[j][3]));
        }
        mt0 = fmaxf(mt0, __shfl_xor_sync(0xffffffffu, mt0, 1));
        mt0 = fmaxf(mt0, __shfl_xor_sync(0xffffffffu, mt0, 2));
        mt1 = fmaxf(mt1, __shfl_xor_sync(0xffffffffu, mt1, 1));
        mt1 = fmaxf(mt1, __shfl_xor_sync(0xffffffffu, mt1, 2));
        float mn0 = fmaxf(m0, mt0), mn1 = fmaxf(m1, mt1);
        float a0 = __expf(m0 - mn0), a1 = __expf(m1 - mn1);
        m0 = mn0; m1 = mn1;

        float rs0 = 0.0f, rs1 = 0.0f;
        unsigned pah[4][4], pal[4][4];
        #pragma unroll
        for (int j = 0; j < 8; j++) {
            float p0 = __expf(s[j][0] - mn0);
            float p1 = __expf(s[j][1] - mn0);
            float p2 = __expf(s[j][2] - mn1);
            float p3 = __expf(s[j][3] - mn1);
            rs0 += p0 + p1; rs1 += p2 + p3;
            unsigned h01 = packbf2(p1, p0);
            unsigned h23 = packbf2(p3, p2);
            float q0f = __uint_as_float(h01 << 16);
            float q1f = __uint_as_float(h01 & 0xffff0000u);
            float q2f = __uint_as_float(h23 << 16);
            float q3f = __uint_as_float(h23 & 0xffff0000u);
            unsigned lo01 = packbf2(p1 - q1f, p0 - q0f);
            unsigned lo23 = packbf2(p3 - q3f, p2 - q2f);
            int t = j >> 1, half = j & 1;
            pah[t][2 * half + 0] = h01;
            pah[t][2 * half + 1] = h23;
            pal[t][2 * half + 0] = lo01;
            pal[t][2 * half + 1] = lo23;
        }
        rs0 += __shfl_xor_sync(0xffffffffu, rs0, 1);
        rs0 += __shfl_xor_sync(0xffffffffu, rs0, 2);
        rs1 += __shfl_xor_sync(0xffffffffu, rs1, 1);
        rs1 += __shfl_xor_sync(0xffffffffu, rs1, 2);
        l0 = l0 * a0 + rs0;
        l1 = l1 * a1 + rs1;
        #pragma unroll
        for (int j = 0; j < 8; j++) {
            o[j][0] *= a0; o[j][1] *= a0;
            o[j][2] *= a1; o[j][3] *= a1;
        }

        #pragma unroll
        for (int jn = 0; jn < 8; jn++) {
            unsigned vbh[8], vbl[8];
            ldsm_x4_t(&vbh[0], sbase + (so + OVH + lane * RS + 8 * jn) * 2);
            ldsm_x4_t(&vbh[4], sbase + (so + OVH + (32 + lane) * RS + 8 * jn) * 2);
            ldsm_x4_t(&vbl[0], sbase + (so + OVL + lane * RS + 8 * jn) * 2);
            ldsm_x4_t(&vbl[4], sbase + (so + OVL + (32 + lane) * RS + 8 * jn) * 2);
            #pragma unroll
            for (int t = 0; t < 4; t++) {
                mma_bf16(o[jn], pah[t], vbh[2*t], vbh[2*t+1]);
                mma_bf16(o[jn], pah[t], vbl[2*t], vbl[2*t+1]);
                mma_bf16(o[jn], pal[t], vbh[2*t], vbh[2*t+1]);
            }
        }

        __syncthreads();
        prefetch(kt + 2);
    }

    float il0 = 1.0f / l0, il1 = 1.0f / l1;
    #pragma unroll
    for (int jn = 0; jn < 8; jn++) {
        int col = 8 * jn + 2 * (lane & 3);
        float f00 = o[jn][0] * il0, f01 = o[jn][1] * il0;
        float f10 = o[jn][2] * il1, f11 = o[jn][3] * il1;
        *(float2*)(merged + ((size_t)(b * SEQ + r_lo) * DIM) + h * HD + col) =
            make_float2(f00, f01);
        *(float2*)(merged + ((size_t)(b * SEQ + r_hi) * DIM) + h * HD + col) =
            make_float2(f10, f11);
        if (write_attn) {
            *(float2*)(attn_out + (((size_t)(b * NH + h) * SEQ + r_lo) * HD) + col) =
                make_float2(f00, f01);
            *(float2*)(attn_out + (((size_t)(b * NH + h) * SEQ + r_hi) * HD) + col) =
                make_float2(f10, f11);
        }
    }
}

// ---------------------------------------------------------------------------
extern "C" void kernel_launch(void* const* d_in, const int* in_sizes, int n_in,
                              void* d_out, int out_size)
{
    const float* q  = (const float*)d_in[0];
    const float* k  = (const float*)d_in[1];
    const float* v  = (const float*)d_in[2];
    const float* Wq = (const float*)d_in[3];
    const float* Wk = (const float*)d_in[4];
    const float* Wv = (const float*)d_in[5];
    const float* Wo = (const float*)d_in[6];
    const int* masked = (const int*)d_in[7];
    float* out = (float*)d_out;

    float *pM, *pWt;
    __nv_bfloat16 *pQh, *pQl, *pKh, *pKl, *pVh, *pVl;
    cudaGetSymbolAddress((void**)&pM,  g_M);
    cudaGetSymbolAddress((void**)&pWt, g_Wt);
    cudaGetSymbolAddress((void**)&pQh, g_Qh);
    cudaGetSymbolAddress((void**)&pQl, g_Ql);
    cudaGetSymbolAddress((void**)&pKh, g_Kh);
    cudaGetSymbolAddress((void**)&pKl, g_Kl);
    cudaGetSymbolAddress((void**)&pVh, g_Vh);
    cudaGetSymbolAddress((void**)&pVl, g_Vl);

    cudaFuncSetAttribute(qkv_gemm, cudaFuncAttributeMaxDynamicSharedMemorySize,
                         GEMM_SMEM);
    cudaFuncSetAttribute(wo_gemm, cudaFuncAttributeMaxDynamicSharedMemorySize,
                         GEMM_SMEM);

    // Pre-pass: transpose + RNA-round all 4 weight matrices
    dim3 gTr(DIM / 32, DIM / 32, 4);
    wtrans<<<gTr, dim3(32, 32)>>>(Wq, Wk, Wv, Wo, pWt);

    // Fused Q/K/V projections (ldmatrix tf32, GBK=32, 3-stage single-barrier)
    dim3 gQKV(DIM / GBN, NTOK / GBM, 3);   // (8, 32, 3)
    qkv_gemm<<<gQKV, 256, GEMM_SMEM>>>(q, k, v, pWt,
                                       pQh, pQl, pKh, pKl, pVh, pVl);

    // Attention (exact R8 config)
    int write_attn = (out_size >= (int)(2 * NELEM)) ? 1 : 0;
    float* attn_ptr = out + NELEM;
    size_t fl_smem = (size_t)SB_TOTAL * sizeof(__nv_bfloat16);
    cudaFuncSetAttribute(flash_bf16, cudaFuncAttributeMaxDynamicSharedMemorySize,
                         (int)fl_smem);
    dim3 gAttn(SEQ / 64, NH, BSZ);         // (32, 16, 2)
    flash_bf16<<<gAttn, 128, fl_smem>>>(pQh, pQl, pKh, pKl, pVh, pVl,
                                        pM, attn_ptr, write_attn, masked);

    // Output projection
    dim3 gWo(DIM / GBN, NTOK / GBM);       // (8, 32)
    wo_gemm<<<gWo, 256, GEMM_SMEM>>>(pM, pWt, out);
}

// round 17
// speedup vs baseline: 1.0744x; 1.0467x over previous
#include <cuda_runtime.h>
#include <cuda_bf16.h>
#include <math.h>

#define BSZ 2
#define SEQ 2048
#define DIM 1024
#define NH  16
#define HD  64
#define NTOK (BSZ*SEQ)            // 4096
#define NELEM ((size_t)NTOK*DIM)  // 4,194,304
#define WELEM ((size_t)DIM*DIM)   // 1,048,576

// Scratch (allocation-free rule: __device__ globals)
__device__ float g_M[NELEM];               // merged attention output [B,S,H*HD]
__device__ float g_Wt[4*WELEM];            // transposed+RNA-rounded weights [n][k]
__device__ __nv_bfloat16 g_Qh[NELEM], g_Ql[NELEM];
__device__ __nv_bfloat16 g_Kh[NELEM], g_Kl[NELEM];
__device__ __nv_bfloat16 g_Vh[NELEM], g_Vl[NELEM];

// ---------------------------------------------------------------------------
// small PTX helpers
// ---------------------------------------------------------------------------
__device__ __forceinline__ unsigned f2tf32(float f) {
    unsigned r;
    asm("cvt.rna.tf32.f32 %0, %1;" : "=r"(r) : "f"(f));
    return r;
}
__device__ __forceinline__ unsigned packbf2(float hi, float lo) {
    unsigned d;
    asm("cvt.rn.bf16x2.f32 %0, %1, %2;" : "=r"(d) : "f"(hi), "f"(lo));
    return d;
}
__device__ __forceinline__ void cp_async16(unsigned smem_addr, const void* gptr) {
    asm volatile("cp.async.cg.shared.global [%0], [%1], 16;\n"
                 :: "r"(smem_addr), "l"(gptr));
}
__device__ __forceinline__ void cp_commit() {
    asm volatile("cp.async.commit_group;\n");
}
template <int N>
__device__ __forceinline__ void cp_wait() {
    asm volatile("cp.async.wait_group %0;\n" :: "n"(N));
}
__device__ __forceinline__ void ldsm_x4(unsigned* r, unsigned addr) {
    asm volatile("ldmatrix.sync.aligned.m8n8.x4.shared.b16 {%0,%1,%2,%3}, [%4];"
                 : "=r"(r[0]), "=r"(r[1]), "=r"(r[2]), "=r"(r[3]) : "r"(addr));
}
__device__ __forceinline__ void ldsm_x4_t(unsigned* r, unsigned addr) {
    asm volatile("ldmatrix.sync.aligned.m8n8.x4.trans.shared.b16 {%0,%1,%2,%3}, [%4];"
                 : "=r"(r[0]), "=r"(r[1]), "=r"(r[2]), "=r"(r[3]) : "r"(addr));
}
__device__ __forceinline__ void mma_bf16(float* c, const unsigned* a,
                                         unsigned b0, unsigned b1) {
    asm volatile(
        "mma.sync.aligned.m16n8k16.row.col.f32.bf16.bf16.f32 "
        "{%0,%1,%2,%3},{%4,%5,%6,%7},{%8,%9},{%0,%1,%2,%3};"
        : "+f"(c[0]), "+f"(c[1]), "+f"(c[2]), "+f"(c[3])
        : "r"(a[0]), "r"(a[1]), "r"(a[2]), "r"(a[3]), "r"(b0), "r"(b1));
}
__device__ __forceinline__ void mma_tf32(float* c, const unsigned* a,
                                         unsigned b0, unsigned b1) {
    asm volatile(
        "mma.sync.aligned.m16n8k8.row.col.f32.tf32.tf32.f32 "
        "{%0,%1,%2,%3},{%4,%5,%6,%7},{%8,%9},{%0,%1,%2,%3};"
        : "+f"(c[0]), "+f"(c[1]), "+f"(c[2]), "+f"(c[3])
        : "r"(a[0]), "r"(a[1]), "r"(a[2]), "r"(a[3]), "r"(b0), "r"(b1));
}

// ---------------------------------------------------------------------------
// Pre-pass: W[k][n] -> Wt[n][k], RNA-rounded to the tf32 grid (fp32 storage).
// ---------------------------------------------------------------------------
__global__ void __launch_bounds__(1024)
wtrans(const float* __restrict__ Wq, const float* __restrict__ Wk,
       const float* __restrict__ Wv, const float* __restrict__ Wo,
       float* __restrict__ Wt)
{
    __shared__ float t[32][33];
    const int z = blockIdx.z;
    const float* W = (z == 0) ? Wq : (z == 1) ? Wk : (z == 2) ? Wv : Wo;
    const int n0 = blockIdx.x * 32, k0 = blockIdx.y * 32;
    const int tx = threadIdx.x, ty = threadIdx.y;

    t[ty][tx] = W[(size_t)(k0 + ty) * DIM + n0 + tx];
    __syncthreads();
    float val = t[tx][ty];   // = W[k0+tx][n0+ty] = Wt[n0+ty][k0+tx]
    Wt[(size_t)z * WELEM + (size_t)(n0 + ty) * DIM + k0 + tx] =
        __uint_as_float(f2tf32(val));
}

// ---------------------------------------------------------------------------
// TF32 GEMM core, ldmatrix operand path (R14-proven):
//   C[M,N] = A[M,K] @ B,  A row-major fp32 (raw; RNA cvt on fragments),
//   B given as Bt[n][k] fp32 (pre-rounded by wtrans).
// 64x128 CTA tile, 128 threads (4 warps, 32x64 warp tile), GBK=32,
// 2-stage cp.async, 4 CTAs/SM. Inner loop: 6 LDSM.x4 + 8 CVT + 16 MMA.
// Row stride 144B = 9 x 16B chunks -> every LDSM phase is bank-conflict-free.
// ---------------------------------------------------------------------------
#define GBM 64
#define GBN 128
#define GBK 32
#define TRS 36                              // row stride in floats (144 B)
#define STAGE_FLOATS ((GBM + GBN) * TRS)    // (64+128)*36 = 6912
#define GEMM_SMEM (2*STAGE_FLOATS*4)        // 55296 B

__device__ __forceinline__ void gemm_core(
    const float* __restrict__ A, const float* __restrict__ Bt,
    float* __restrict__ Cf,
    __nv_bfloat16* __restrict__ Ch, __nv_bfloat16* __restrict__ Cl,
    float scale, int M, int N, int K, float* sm)
{
    const int tid  = threadIdx.x;
    const int lane = tid & 31;
    const int warp = tid >> 5;           // 0..3
    const int wm   = warp >> 1;          // 0..1 (32 rows)
    const int wn   = warp & 1;           // 0..1 (64 cols)

    const int mBase = blockIdx.y * GBM;
    const int nBase = blockIdx.x * GBN;

    const float* Ab = A  + (size_t)mBase * K;
    const float* Bb = Bt + (size_t)nBase * K;

    unsigned smem_base;
    asm("{ .reg .u64 t; cvta.to.shared.u64 t, %1; cvt.u32.u64 %0, t; }"
        : "=r"(smem_base) : "l"(sm));

    float c[2][8][4];
    #pragma unroll
    for (int mt = 0; mt < 2; mt++)
        #pragma unroll
        for (int nt = 0; nt < 8; nt++)
            #pragma unroll
            for (int e = 0; e < 4; e++) c[mt][nt][e] = 0.0f;

    const int niter = K / GBK;           // 32

    // cp.async: A 64 rows x 8 chunks = 512; B 128 rows x 8 chunks = 1024
    auto load_stage = [&](int iter, int buf) {
        const int k0 = iter * GBK;
        unsigned aBase = smem_base + (unsigned)(buf * STAGE_FLOATS) * 4u;
        unsigned bBase = aBase + GBM * TRS * 4u;
        #pragma unroll
        for (int it = 0; it < 4; it++) {
            int idx = tid + 128 * it;    // 0..511
            int r = idx >> 3, ch = idx & 7;
            cp_async16(aBase + (unsigned)(r * 144 + ch * 16),
                       Ab + (size_t)r * K + k0 + ch * 4);
        }
        #pragma unroll
        for (int it = 0; it < 8; it++) {
            int idx = tid + 128 * it;    // 0..1023
            int r = idx >> 3, ch = idx & 7;
            cp_async16(bBase + (unsigned)(r * 144 + ch * 16),
                       Bb + (size_t)r * K + k0 + ch * 4);
        }
    };

    load_stage(0, 0); cp_commit();
    load_stage(1, 1); cp_commit();

    // Precompute per-lane ldmatrix addresses (relative to region bases)
    unsigned aOff[2], bOff[4];
    {
        int arow_l = (lane & 7) + ((lane >> 3) & 1) * 8;   // row within 16
        int achk   = ((lane >> 4) & 1) * 16;               // 0 or 16 B
        #pragma unroll
        for (int mt = 0; mt < 2; mt++) {
            int row = wm * 32 + mt * 16 + arow_l;
            aOff[mt] = (unsigned)(row * 144 + achk);
        }
        int brow_l = (lane & 7) + ((lane >> 4) & 1) * 8;   // row within 16
        int bchk   = ((lane >> 3) & 1) * 16;               // 0 or 16 B
        #pragma unroll
        for (int p = 0; p < 4; p++) {
            int row = wn * 64 + p * 16 + brow_l;
            bOff[p] = (unsigned)(row * 144 + bchk);
        }
    }

    for (int i = 0; i < niter; i++) {
        cp_wait<1>();
        __syncthreads();

        const int buf = i & 1;
        unsigned aBase = smem_base + (unsigned)(buf * STAGE_FLOATS) * 4u;
        unsigned bBase = aBase + GBM * TRS * 4u;

        #pragma unroll
        for (int kk = 0; kk < GBK / 8; kk++) {
            unsigned koff = (unsigned)(kk * 32);   // 8 tf32 = 32 B
            unsigned af[2][4], bf[4][4];
            #pragma unroll
            for (int mt = 0; mt < 2; mt++) {
                ldsm_x4(af[mt], aBase + aOff[mt] + koff);
                #pragma unroll
                for (int e = 0; e < 4; e++)
                    af[mt][e] = f2tf32(__uint_as_float(af[mt][e]));
            }
            #pragma unroll
            for (int p = 0; p < 4; p++)
                ldsm_x4(bf[p], bBase + bOff[p] + koff);

            #pragma unroll
            for (int mt = 0; mt < 2; mt++)
                #pragma unroll
                for (int nt = 0; nt < 8; nt++)
                    mma_tf32(c[mt][nt], af[mt],
                             bf[nt >> 1][2 * (nt & 1)],
                             bf[nt >> 1][2 * (nt & 1) + 1]);
        }
        __syncthreads();
        if (i + 2 < niter) load_stage(i + 2, buf);
        cp_commit();
    }

    // Epilogue (same c-frag mapping as R8/R14)
    const int g  = lane >> 2;
    const int tg = lane & 3;
    if (Ch) {
        #pragma unroll
        for (int mt = 0; mt < 2; mt++) {
            int r0 = mBase + wm * 32 + mt * 16 + g;
            #pragma unroll
            for (int nt = 0; nt < 8; nt++) {
                int col = nBase + wn * 64 + nt * 8 + 2 * tg;
                #pragma unroll
                for (int half = 0; half < 2; half++) {
                    size_t off = (size_t)(r0 + 8 * half) * N + col;
                    float y0 = c[mt][nt][2 * half + 0] * scale;
                    float y1 = c[mt][nt][2 * half + 1] * scale;
                    unsigned hi = packbf2(y1, y0);
                    float h0 = __uint_as_float(hi << 16);
                    float h1 = __uint_as_float(hi & 0xffff0000u);
                    unsigned lo = packbf2(y1 - h1, y0 - h0);
                    *(unsigned*)(Ch + off) = hi;
                    *(unsigned*)(Cl + off) = lo;
                }
            }
        }
    } else {
        #pragma unroll
        for (int mt = 0; mt < 2; mt++) {
            int r0 = mBase + wm * 32 + mt * 16 + g;
            #pragma unroll
            for (int nt = 0; nt < 8; nt++) {
                int col = nBase + wn * 64 + nt * 8 + 2 * tg;
                *(float2*)(Cf + (size_t)r0 * N + col) =
                    make_float2(c[mt][nt][0], c[mt][nt][1]);
                *(float2*)(Cf + (size_t)(r0 + 8) * N + col) =
                    make_float2(c[mt][nt][2], c[mt][nt][3]);
            }
        }
    }
}

// Fused Q/K/V projections: grid.z selects the GEMM.
__global__ void __launch_bounds__(128, 4)
qkv_gemm(const float* __restrict__ q, const float* __restrict__ k,
         const float* __restrict__ v, const float* __restrict__ Wt,
         __nv_bfloat16* Qh, __nv_bfloat16* Ql,
         __nv_bfloat16* Kh, __nv_bfloat16* Kl,
         __nv_bfloat16* Vh, __nv_bfloat16* Vl)
{
    extern __shared__ float sm[];
    const int z = blockIdx.z;
    const float* A = (z == 0) ? q  : (z == 1) ? k  : v;
    __nv_bfloat16* Ch = (z == 0) ? Qh : (z == 1) ? Kh : Vh;
    __nv_bfloat16* Cl = (z == 0) ? Ql : (z == 1) ? Kl : Vl;
    float scale = (z == 0) ? 0.125f : 1.0f;
    gemm_core(A, Wt + (size_t)z * WELEM, nullptr, Ch, Cl, scale,
              NTOK, DIM, DIM, sm);
}

__global__ void __launch_bounds__(128, 4)
wo_gemm(const float* __restrict__ A, const float* __restrict__ Wt,
        float* __restrict__ C)
{
    extern __shared__ float sm[];
    gemm_core(A, Wt + 3 * WELEM, C, nullptr, nullptr, 1.0f,
              NTOK, DIM, DIM, sm);
}

// ---------------------------------------------------------------------------
// Flash attention (exact R8 config — best measured): bf16 tensor cores,
// 3-term hi/lo split, 128-thread CTAs over 64 q-rows, 2 CTAs/SM,
// gmem-direct Q frags, 2-stage cp.async KV double-buffer, padded smem.
// ---------------------------------------------------------------------------
#define RS 72
#define KVSTAGE (4*64*RS)              // 18432 bf16 per stage
#define SB_TOTAL (2*KVSTAGE)           // 73728 B
#define OKH 0
#define OKL (64*RS)
#define OVH (128*RS)
#define OVL (192*RS)

__global__ void __launch_bounds__(128, 2)
flash_bf16(const __nv_bfloat16* __restrict__ Qh, const __nv_bfloat16* __restrict__ Ql,
           const __nv_bfloat16* __restrict__ Kh, const __nv_bfloat16* __restrict__ Kl,
           const __nv_bfloat16* __restrict__ Vh, const __nv_bfloat16* __restrict__ Vl,
           float* __restrict__ merged, float* __restrict__ attn_out,
           int write_attn, const int* __restrict__ maskedp)
{
    extern __shared__ __nv_bfloat16 sb[];
    const int qt  = gridDim.x - 1 - blockIdx.x;   // heavy blocks first
    const int h   = blockIdx.y;
    const int b   = blockIdx.z;
    const int tid = threadIdx.x;
    const int lane = tid & 31;
    const int w   = tid >> 5;                     // 0..3
    const int q0  = qt * 64;
    const int masked = maskedp[0];

    unsigned sbase;
    asm("{ .reg .u64 t; cvta.to.shared.u64 t, %1; cvt.u32.u64 %0, t; }"
        : "=r"(sbase) : "l"(sb));

    const int ktmax = masked ? qt : (SEQ / 64 - 1);

    auto stage_off = [](int kt) -> unsigned { return (kt & 1) ? (unsigned)KVSTAGE : 0u; };

    auto prefetch = [&](int t) {
        if (t <= ktmax) {
            unsigned so = stage_off(t);
            int r  = tid >> 3;
            int c8 = (tid & 7) << 3;
            #pragma unroll
            for (int quarter = 0; quarter < 4; quarter++) {
                int rr = r + 16 * quarter;
                size_t gidx = ((size_t)(b * SEQ + t * 64 + rr) * DIM) + h * HD + c8;
                unsigned sa = sbase + (so + rr * RS + c8) * 2;
                cp_async16(sa + OKH * 2, Kh + gidx);
                cp_async16(sa + OKL * 2, Kl + gidx);
                cp_async16(sa + OVH * 2, Vh + gidx);
                cp_async16(sa + OVL * 2, Vl + gidx);
            }
        }
        cp_commit();
    };

    prefetch(0);
    prefetch(1);

    unsigned qf[2][4][4];
    {
        const int g  = lane >> 2;
        const int tg = lane & 3;
        const int row0 = q0 + 16 * w + g;
        size_t base0 = ((size_t)(b * SEQ + row0)     * DIM) + h * HD;
        size_t base1 = ((size_t)(b * SEQ + row0 + 8) * DIM) + h * HD;
        #pragma unroll
        for (int d = 0; d < 4; d++) {
            int c0 = 16 * d + 2 * tg;
            qf[0][d][0] = *(const unsigned*)(Qh + base0 + c0);
            qf[0][d][1] = *(const unsigned*)(Qh + base1 + c0);
            qf[0][d][2] = *(const unsigned*)(Qh + base0 + c0 + 8);
            qf[0][d][3] = *(const unsigned*)(Qh + base1 + c0 + 8);
            qf[1][d][0] = *(const unsigned*)(Ql + base0 + c0);
            qf[1][d][1] = *(const unsigned*)(Ql + base1 + c0);
            qf[1][d][2] = *(const unsigned*)(Ql + base0 + c0 + 8);
            qf[1][d][3] = *(const unsigned*)(Ql + base1 + c0 + 8);
        }
    }

    float o[8][4];
    #pragma unroll
    for (int j = 0; j < 8; j++)
        #pragma unroll
        for (int e = 0; e < 4; e++) o[j][e] = 0.0f;
    float m0 = -1e30f, m1 = -1e30f, l0 = 0.0f, l1 = 0.0f;

    const int r_lo = q0 + 16 * w + (lane >> 2);
    const int r_hi = r_lo + 8;

    for (int kt = 0; kt <= ktmax; kt++) {
        cp_wait<1>();
        __syncthreads();

        const unsigned so = stage_off(kt);
        const int k0 = kt * 64;

        float s[8][4];
        #pragma unroll
        for (int j = 0; j < 8; j++)
            #pragma unroll
            for (int e = 0; e < 4; e++) s[j][e] = 0.0f;

        #pragma unroll
        for (int j = 0; j < 8; j++) {
            unsigned kbh[8], kbl[8];
            int krow = 8 * j + (lane & 7);
            int dct  = (lane >> 3) << 3;
            ldsm_x4(&kbh[0], sbase + (so + OKH + krow * RS + dct) * 2);
            ldsm_x4(&kbh[4], sbase + (so + OKH + krow * RS + 32 + dct) * 2);
            ldsm_x4(&kbl[0], sbase + (so + OKL + krow * RS + dct) * 2);
            ldsm_x4(&kbl[4], sbase + (so + OKL + krow * RS + 32 + dct) * 2);
            #pragma unroll
            for (int d = 0; d < 4; d++) {
                mma_bf16(s[j], qf[0][d], kbh[2*d], kbh[2*d+1]);
                mma_bf16(s[j], qf[0][d], kbl[2*d], kbl[2*d+1]);
                mma_bf16(s[j], qf[1][d], kbh[2*d], kbh[2*d+1]);
            }
        }

        if (masked && kt == qt) {
            #pragma unroll
            for (int j = 0; j < 8; j++) {
                int cc = k0 + 8 * j + 2 * (lane & 3);
                if (cc     > r_lo) s[j][0] = -1e30f;
                if (cc + 1 > r_lo) s[j][1] = -1e30f;
                if (cc     > r_hi) s[j][2] = -1e30f;
                if (cc + 1 > r_hi) s[j][3] = -1e30f;
            }
        }

        float mt0 = -1e30f, mt1 = -1e30f;
        #pragma unroll
        for (int j = 0; j < 8; j++) {
            mt0 = fmaxf(mt0, fmaxf(s[j][0], s[j][1]));
            mt1 = fmaxf(mt1, fmaxf(s[j][2], s[j][3]));
        }
        mt0 = fmaxf(mt0, __shfl_xor_sync(0xffffffffu, mt0, 1));
        mt0 = fmaxf(mt0, __shfl_xor_sync(0xffffffffu, mt0, 2));
        mt1 = fmaxf(mt1, __shfl_xor_sync(0xffffffffu, mt1, 1));
        mt1 = fmaxf(mt1, __shfl_xor_sync(0xffffffffu, mt1, 2));
        float mn0 = fmaxf(m0, mt0), mn1 = fmaxf(m1, mt1);
        float a0 = __expf(m0 - mn0), a1 = __expf(m1 - mn1);
        m0 = mn0; m1 = mn1;

        float rs0 = 0.0f, rs1 = 0.0f;
        unsigned pah[4][4], pal[4][4];
        #pragma unroll
        for (int j = 0; j < 8; j++) {
            float p0 = __expf(s[j][0] - mn0);
            float p1 = __expf(s[j][1] - mn0);
            float p2 = __expf(s[j][2] - mn1);
            float p3 = __expf(s[j][3] - mn1);
            rs0 += p0 + p1; rs1 += p2 + p3;
            unsigned h01 = packbf2(p1, p0);
            unsigned h23 = packbf2(p3, p2);
            float q0f = __uint_as_float(h01 << 16);
            float q1f = __uint_as_float(h01 & 0xffff0000u);
            float q2f = __uint_as_float(h23 << 16);
            float q3f = __uint_as_float(h23 & 0xffff0000u);
            unsigned lo01 = packbf2(p1 - q1f, p0 - q0f);
            unsigned lo23 = packbf2(p3 - q3f, p2 - q2f);
            int t = j >> 1, half = j & 1;
            pah[t][2 * half + 0] = h01;
            pah[t][2 * half + 1] = h23;
            pal[t][2 * half + 0] = lo01;
            pal[t][2 * half + 1] = lo23;
        }
        rs0 += __shfl_xor_sync(0xffffffffu, rs0, 1);
        rs0 += __shfl_xor_sync(0xffffffffu, rs0, 2);
        rs1 += __shfl_xor_sync(0xffffffffu, rs1, 1);
        rs1 += __shfl_xor_sync(0xffffffffu, rs1, 2);
        l0 = l0 * a0 + rs0;
        l1 = l1 * a1 + rs1;
        #pragma unroll
        for (int j = 0; j < 8; j++) {
            o[j][0] *= a0; o[j][1] *= a0;
            o[j][2] *= a1; o[j][3] *= a1;
        }

        #pragma unroll
        for (int jn = 0; jn < 8; jn++) {
            unsigned vbh[8], vbl[8];
            ldsm_x4_t(&vbh[0], sbase + (so + OVH + lane * RS + 8 * jn) * 2);
            ldsm_x4_t(&vbh[4], sbase + (so + OVH + (32 + lane) * RS + 8 * jn) * 2);
            ldsm_x4_t(&vbl[0], sbase + (so + OVL + lane * RS + 8 * jn) * 2);
            ldsm_x4_t(&vbl[4], sbase + (so + OVL + (32 + lane) * RS + 8 * jn) * 2);
            #pragma unroll
            for (int t = 0; t < 4; t++) {
                mma_bf16(o[jn], pah[t], vbh[2*t], vbh[2*t+1]);
                mma_bf16(o[jn], pah[t], vbl[2*t], vbl[2*t+1]);
                mma_bf16(o[jn], pal[t], vbh[2*t], vbh[2*t+1]);
            }
        }

        __syncthreads();
        prefetch(kt + 2);
    }

    float il0 = 1.0f / l0, il1 = 1.0f / l1;
    #pragma unroll
    for (int jn = 0; jn < 8; jn++) {
        int col = 8 * jn + 2 * (lane & 3);
        float f00 = o[jn][0] * il0, f01 = o[jn][1] * il0;
        float f10 = o[jn][2] * il1, f11 = o[jn][3] * il1;
        *(float2*)(merged + ((size_t)(b * SEQ + r_lo) * DIM) + h * HD + col) =
            make_float2(f00, f01);
        *(float2*)(merged + ((size_t)(b * SEQ + r_hi) * DIM) + h * HD + col) =
            make_float2(f10, f11);
        if (write_attn) {
            *(float2*)(attn_out + (((size_t)(b * NH + h) * SEQ + r_lo) * HD) + col) =
                make_float2(f00, f01);
            *(float2*)(attn_out + (((size_t)(b * NH + h) * SEQ + r_hi) * HD) + col) =
                make_float2(f10, f11);
        }
    }
}

// ---------------------------------------------------------------------------
extern "C" void kernel_launch(void* const* d_in, const int* in_sizes, int n_in,
                              void* d_out, int out_size)
{
    const float* q  = (const float*)d_in[0];
    const float* k  = (const float*)d_in[1];
    const float* v  = (const float*)d_in[2];
    const float* Wq = (const float*)d_in[3];
    const float* Wk = (const float*)d_in[4];
    const float* Wv = (const float*)d_in[5];
    const float* Wo = (const float*)d_in[6];
    const int* masked = (const int*)d_in[7];
    float* out = (float*)d_out;

    float *pM, *pWt;
    __nv_bfloat16 *pQh, *pQl, *pKh, *pKl, *pVh, *pVl;
    cudaGetSymbolAddress((void**)&pM,  g_M);
    cudaGetSymbolAddress((void**)&pWt, g_Wt);
    cudaGetSymbolAddress((void**)&pQh, g_Qh);
    cudaGetSymbolAddress((void**)&pQl, g_Ql);
    cudaGetSymbolAddress((void**)&pKh, g_Kh);
    cudaGetSymbolAddress((void**)&pKl, g_Kl);
    cudaGetSymbolAddress((void**)&pVh, g_Vh);
    cudaGetSymbolAddress((void**)&pVl, g_Vl);

    cudaFuncSetAttribute(qkv_gemm, cudaFuncAttributeMaxDynamicSharedMemorySize,
                         GEMM_SMEM);
    cudaFuncSetAttribute(wo_gemm, cudaFuncAttributeMaxDynamicSharedMemorySize,
                         GEMM_SMEM);

    // Pre-pass: transpose + RNA-round all 4 weight matrices
    dim3 gTr(DIM / 32, DIM / 32, 4);
    wtrans<<<gTr, dim3(32, 32)>>>(Wq, Wk, Wv, Wo, pWt);

    // Fused Q/K/V projections (ldmatrix tf32 core)
    dim3 gQKV(DIM / GBN, NTOK / GBM, 3);   // (8, 64, 3)
    qkv_gemm<<<gQKV, 128, GEMM_SMEM>>>(q, k, v, pWt,
                                       pQh, pQl, pKh, pKl, pVh, pVl);

    // Attention (exact R8 config)
    int write_attn = (out_size >= (int)(2 * NELEM)) ? 1 : 0;
    float* attn_ptr = out + NELEM;
    size_t fl_smem = (size_t)SB_TOTAL * sizeof(__nv_bfloat16);
    cudaFuncSetAttribute(flash_bf16, cudaFuncAttributeMaxDynamicSharedMemorySize,
                         (int)fl_smem);
    dim3 gAttn(SEQ / 64, NH, BSZ);         // (32, 16, 2)
    flash_bf16<<<gAttn, 128, fl_smem>>>(pQh, pQl, pKh, pKl, pVh, pVl,
                                        pM, attn_ptr, write_attn, masked);

    // Output projection (ldmatrix tf32 core)
    dim3 gWo(DIM / GBN, NTOK / GBM);       // (8, 64)
    wo_gemm<<<gWo, 128, GEMM_SMEM>>>(pM, pWt, out);
}